// round 16
// baseline (speedup 1.0000x reference)
#include <cuda_runtime.h>
#include <cuda_fp16.h>
#include <cstddef>

#define NB 64
#define NT 1024
#define NC 64
#define NH 4
#define ND 16

typedef unsigned long long u64;

// Scratch (device globals — no allocation allowed)
__device__ float  g_q  [(size_t)NB * NT * 64];             // [n][64] fp32 Q, c = h*16+d
__device__ __half g_kh [(size_t)NB * NH * NT * ND];        // [bh][t][d] f16 hi
__device__ __half g_kl [(size_t)NB * NH * NT * ND];        // [bh][t][d] f16 lo
__device__ __half g_vth[(size_t)NB * NH * ND * NT];        // [bh][d][t] f16 (transposed)
__device__ float  g_att[(size_t)NB * NT * NC];             // [n][64] attention out
// Pre-split weights (computed once by splitw_kernel)
__device__ __half g_wqh[192 * 64];                         // w_qkv hi
__device__ __half g_wql[192 * 64];                         // w_qkv lo
__device__ __half g_wph[64 * 64];                          // w_proj hi
__device__ __half g_wpl[64 * 64];                          // w_proj lo

// ---- cp.async helpers ------------------------------------------------------
__device__ __forceinline__ void cp_async16(void* smem, const void* gptr) {
    unsigned s = (unsigned)__cvta_generic_to_shared(smem);
    asm volatile("cp.async.ca.shared.global [%0], [%1], 16;" :: "r"(s), "l"(gptr));
}
__device__ __forceinline__ void cp_commit() { asm volatile("cp.async.commit_group;"); }
__device__ __forceinline__ void cp_wait1()  { asm volatile("cp.async.wait_group 1;"); }
__device__ __forceinline__ void cp_wait0()  { asm volatile("cp.async.wait_group 0;"); }

// ---- misc ------------------------------------------------------------------
__device__ __forceinline__ unsigned ex2h2(unsigned x) {   // 2x f16 exp2 in one MUFU
    unsigned r;
    asm("ex2.approx.f16x2 %0, %1;" : "=r"(r) : "r"(x));
    return r;
}
__device__ __forceinline__ unsigned h2u(__half2 h) { return *(unsigned*)&h; }

// mma.sync m16n8k16 f16 inputs, f32 accum. D and C may alias.
__device__ __forceinline__ void mma16816(float* d, const unsigned* a,
                                         unsigned b0, unsigned b1, const float* c) {
    asm volatile(
        "mma.sync.aligned.m16n8k16.row.col.f32.f16.f16.f32 "
        "{%0,%1,%2,%3}, {%4,%5,%6,%7}, {%8,%9}, {%10,%11,%12,%13};\n"
        : "=f"(d[0]), "=f"(d[1]), "=f"(d[2]), "=f"(d[3])
        : "r"(a[0]), "r"(a[1]), "r"(a[2]), "r"(a[3]), "r"(b0), "r"(b1),
          "f"(c[0]), "f"(c[1]), "f"(c[2]), "f"(c[3]));
}

__device__ __forceinline__ void split2(float2 v, __half2& hi, __half2& lo) {
    hi = __float22half2_rn(v);
    lo = __float22half2_rn(make_float2(v.x - __low2float(hi), v.y - __high2float(hi)));
}

// ---------------------------------------------------------------------------
// Kernel 0: one-shot weight split (w_qkv 192x64, w_proj 64x64 -> f16 hi/lo).
// ---------------------------------------------------------------------------
__global__ void splitw_kernel(const float* __restrict__ wq,
                              const float* __restrict__ wp) {
    const int i = blockIdx.x * 256 + threadIdx.x;     // float2 index, 0..8191
    if (i < 6144) {
        const float2 v = *(const float2*)&wq[2 * i];
        __half2 hi, lo;
        split2(v, hi, lo);
        *(__half2*)&g_wqh[2 * i] = hi;
        *(__half2*)&g_wql[2 * i] = lo;
    } else {
        const int j = i - 6144;                        // 0..2047
        const float2 v = *(const float2*)&wp[2 * j];
        __half2 hi, lo;
        split2(v, hi, lo);
        *(__half2*)&g_wph[2 * j] = hi;
        *(__half2*)&g_wpl[2 * j] = lo;
    }
}

// ---------------------------------------------------------------------------
// Kernel A: QKV projection via f16-split m16n8k16 mma.
// Block: 384 threads = 12 warps (2 m x 6 n), 64 tokens, all 192 outputs.
// ---------------------------------------------------------------------------
__global__ __launch_bounds__(384) void qkv_kernel(const float* __restrict__ x) {
    extern __shared__ __half smh[];
    __half* Xhi = smh;                    // [64][72]
    __half* Xlo = Xhi + 64 * 72;
    __half* Whi = Xlo + 64 * 72;          // [192][72]
    __half* Wlo = Whi + 192 * 72;

    const int tid = threadIdx.x;
    const int blk = blockIdx.x;           // 0..1023

    for (int i = tid; i < 1536; i += 384) {
        const int row = i >> 3, c = i & 7;
        cp_async16(&Whi[row * 72 + c * 8], g_wqh + row * 64 + c * 8);
        cp_async16(&Wlo[row * 72 + c * 8], g_wql + row * 64 + c * 8);
    }
    cp_commit();

    const float* xsrc = x + (size_t)blk * 4096;
    for (int i = tid; i < 1024; i += 384) {
        const int row = i >> 4, c4 = i & 15;
        const float4 v = *(const float4*)&xsrc[row * 64 + c4 * 4];
        __half2 h01, l01, h23, l23;
        split2(make_float2(v.x, v.y), h01, l01);
        split2(make_float2(v.z, v.w), h23, l23);
        *(__half2*)&Xhi[row * 72 + c4 * 4]     = h01;
        *(__half2*)&Xhi[row * 72 + c4 * 4 + 2] = h23;
        *(__half2*)&Xlo[row * 72 + c4 * 4]     = l01;
        *(__half2*)&Xlo[row * 72 + c4 * 4 + 2] = l23;
    }
    cp_wait0();
    __syncthreads();

    const int warp = tid >> 5, lane = tid & 31;
    const int g = lane >> 2, tig = lane & 3;
    const int wm = warp / 6;              // 0..1
    const int wn = warp % 6;              // 0..5
    const int r0 = wm * 32;
    const int n0 = wn * 32;

    float acc[2][4][4];
    #pragma unroll
    for (int mt = 0; mt < 2; mt++)
        #pragma unroll
        for (int oct = 0; oct < 4; oct++)
            #pragma unroll
            for (int i = 0; i < 4; i++) acc[mt][oct][i] = 0.f;

    #pragma unroll
    for (int kc = 0; kc < 4; kc++) {
        unsigned ahi[2][4], alo[2][4];
        #pragma unroll
        for (int mt = 0; mt < 2; mt++) {
            const int rb = r0 + mt * 16;
            ahi[mt][0] = *(const unsigned*)&Xhi[(rb + g)     * 72 + kc * 16 + 2 * tig];
            ahi[mt][1] = *(const unsigned*)&Xhi[(rb + g + 8) * 72 + kc * 16 + 2 * tig];
            ahi[mt][2] = *(const unsigned*)&Xhi[(rb + g)     * 72 + kc * 16 + 2 * tig + 8];
            ahi[mt][3] = *(const unsigned*)&Xhi[(rb + g + 8) * 72 + kc * 16 + 2 * tig + 8];
            alo[mt][0] = *(const unsigned*)&Xlo[(rb + g)     * 72 + kc * 16 + 2 * tig];
            alo[mt][1] = *(const unsigned*)&Xlo[(rb + g + 8) * 72 + kc * 16 + 2 * tig];
            alo[mt][2] = *(const unsigned*)&Xlo[(rb + g)     * 72 + kc * 16 + 2 * tig + 8];
            alo[mt][3] = *(const unsigned*)&Xlo[(rb + g + 8) * 72 + kc * 16 + 2 * tig + 8];
        }
        #pragma unroll
        for (int oct = 0; oct < 4; oct++) {
            const int col = n0 + oct * 8 + g;
            const unsigned bh0 = *(const unsigned*)&Whi[col * 72 + kc * 16 + 2 * tig];
            const unsigned bh1 = *(const unsigned*)&Whi[col * 72 + kc * 16 + 2 * tig + 8];
            const unsigned bl0 = *(const unsigned*)&Wlo[col * 72 + kc * 16 + 2 * tig];
            const unsigned bl1 = *(const unsigned*)&Wlo[col * 72 + kc * 16 + 2 * tig + 8];
            #pragma unroll
            for (int mt = 0; mt < 2; mt++) {
                mma16816(acc[mt][oct], ahi[mt], bh0, bh1, acc[mt][oct]);
                mma16816(acc[mt][oct], alo[mt], bh0, bh1, acc[mt][oct]);
                mma16816(acc[mt][oct], ahi[mt], bl0, bl1, acc[mt][oct]);
            }
        }
    }

    const int bb  = blk >> 4;
    const int t0i = (blk & 15) * 64;
    #pragma unroll
    for (int mt = 0; mt < 2; mt++) {
        const int trow = r0 + mt * 16 + g;
        #pragma unroll
        for (int oct = 0; oct < 4; oct++) {
            const float* c = acc[mt][oct];
            const int o = n0 + oct * 8 + 2 * tig;
            if (o < 64) {                           // Q fp32 [n][64]
                const size_t base = ((size_t)blk * 64 + trow) * 64 + o;
                *(float2*)&g_q[base]          = make_float2(c[0], c[1]);
                *(float2*)&g_q[base + 8 * 64] = make_float2(c[2], c[3]);
            } else if (o < 128) {                   // K f16 hi/lo [bh][t][d]
                const int hh = (o - 64) >> 4, d = (o - 64) & 15;
                const size_t base =
                    ((size_t)(bb * 4 + hh) * 1024 + t0i + trow) * 16 + d;
                __half2 h01, l01, h23, l23;
                split2(make_float2(c[0], c[1]), h01, l01);
                split2(make_float2(c[2], c[3]), h23, l23);
                *(__half2*)&g_kh[base]          = h01;
                *(__half2*)&g_kl[base]          = l01;
                *(__half2*)&g_kh[base + 8 * 16] = h23;
                *(__half2*)&g_kl[base + 8 * 16] = l23;
            } else {                                // V^T single f16 [bh][d][t]
                const int hh = (o - 128) >> 4, d0 = (o - 128) & 15;
                const size_t t = (size_t)t0i + trow;
                const size_t rowa = ((size_t)(bb * 4 + hh) * 16 + d0) * 1024;
                const size_t rowb = rowa + 1024;
                const __half2 h01 = __float22half2_rn(make_float2(c[0], c[1]));
                const __half2 h23 = __float22half2_rn(make_float2(c[2], c[3]));
                g_vth[rowa + t]     = __low2half(h01);
                g_vth[rowb + t]     = __high2half(h01);
                g_vth[rowa + t + 8] = __low2half(h23);
                g_vth[rowb + t + 8] = __high2half(h23);
            }
        }
    }
}

// ---------------------------------------------------------------------------
// Kernel B: causal flash attention, 128-key double-buffered chunks.
// QK: Q single-f16 x K hi/lo (2 mma); AV: P f16 x V single-f16 (1 mma);
// fixed-max softmax via ex2.approx.f16x2; row sums via ones-MMA.
// Grid (256 bh, 8 qtiles of 128 q), block 256 threads = 8 warps.
// Barriers: 2 per 128 keys (was per 64) -> longer compute stretches.
// ---------------------------------------------------------------------------
#define KPAD 24     // K row pitch (halves)
#define VPAD 136    // V^T row pitch (halves), 128 cols + 8 pad

__device__ __forceinline__ void attn_prefetch(
    __half* KhiB, __half* KloB, __half* VhiB,
    int bh, int ct, int tid)
{
    // K: 128 rows x 2 chunks of 16B, hi + lo
    const size_t kg = ((size_t)bh * 1024 + (size_t)ct * 128) * 16;
    const int r = tid >> 1, c = tid & 1;
    cp_async16(KhiB + r * KPAD + c * 8, g_kh + kg + r * 16 + c * 8);
    cp_async16(KloB + r * KPAD + c * 8, g_kl + kg + r * 16 + c * 8);
    // V: 16 rows x 16 chunks of 16B
    const int d = tid >> 4, vc = tid & 15;
    const size_t vg = ((size_t)bh * 16 + d) * 1024 + (size_t)ct * 128 + vc * 8;
    cp_async16(VhiB + d * VPAD + vc * 8, g_vth + vg);
}

__global__ __launch_bounds__(256) void attn_kernel() {
    __shared__ __align__(16) float  Qs[128 * 16];
    __shared__ __align__(16) __half Khi[2][128 * KPAD];
    __shared__ __align__(16) __half Klo[2][128 * KPAD];
    __shared__ __align__(16) __half Vhi[2][16 * VPAD];

    const int tid  = threadIdx.x;
    const int bh   = blockIdx.x;                 // 0..255
    const int qt   = 7 - (int)blockIdx.y;        // heavy q-tiles first
    const int warp = tid >> 5;                   // 0..7
    const int lane = tid & 31;
    const int g    = lane >> 2;
    const int tig  = lane & 3;
    const int b    = bh >> 2, h = bh & 3;
    const int qbase = qt * 128;

    attn_prefetch(Khi[0], Klo[0], Vhi[0], bh, 0, tid);
    cp_commit();

    // stage Q tile (128 q x 16 d)
    {
        const float* qsrc = g_q + ((size_t)b * 1024 + qbase) * 64 + h * 16;
        for (int i = tid; i < 2048; i += 256) {
            const int ql = i >> 4, d = i & 15;
            Qs[ql * 16 + d] = qsrc[(size_t)ql * 64 + d];
        }
    }
    __syncthreads();

    // Q fragment: single f16, scale = 1/sqrt(16) * log2(e) folded in
    const float qscale = 0.25f * 1.4426950408889634f;
    unsigned aq[4];
    {
        const int r0 = warp * 16 + g;
        #pragma unroll
        for (int i = 0; i < 4; i++) {
            const int r = (i & 1) ? r0 + 8 : r0;
            const int c = (i >> 1) ? 2 * tig + 8 : 2 * tig;
            float2 v = *(const float2*)&Qs[r * 16 + c];
            v.x *= qscale;  v.y *= qscale;
            aq[i] = h2u(__float22half2_rn(v));
        }
    }

    const int qmin = qbase + warp * 16;          // this warp's lowest q row
    const unsigned ONES = 0x3C003C00u;           // (1.0h, 1.0h)
    float ol[4];                                  // ones-mma row sums
    float o[2][4];
    #pragma unroll
    for (int i = 0; i < 4; i++) { ol[i] = 0.f; o[0][i] = 0.f; o[1][i] = 0.f; }

    const int nchunks = qt + 1;
    for (int ct = 0; ct < nchunks; ct++) {
        const int bf = ct & 1;
        if (ct + 1 < nchunks) {
            attn_prefetch(Khi[bf ^ 1], Klo[bf ^ 1], Vhi[bf ^ 1], bh, ct + 1, tid);
            cp_commit();
            cp_wait1();
        } else {
            cp_wait0();
        }
        __syncthreads();

        #pragma unroll
        for (int half = 0; half < 2; half++) {
            const int kbase = ct * 128 + half * 64;
            if (kbase > qmin + 15) break;        // fully masked for this warp

            const __half* KH = Khi[bf] + half * 64 * KPAD;
            const __half* KL = Klo[bf] + half * 64 * KPAD;
            const __half* VH = Vhi[bf] + half * 64;

            // ---- S = Q K^T  (2 mma per octet: q_f16 x (Khi, Klo))
            float s[8][4];
            #pragma unroll
            for (int oct = 0; oct < 8; oct++) {
                const int key = oct * 8 + g;
                const unsigned kh0 = *(const unsigned*)&KH[key * KPAD + 2 * tig];
                const unsigned kh1 = *(const unsigned*)&KH[key * KPAD + 2 * tig + 8];
                const unsigned kl0 = *(const unsigned*)&KL[key * KPAD + 2 * tig];
                const unsigned kl1 = *(const unsigned*)&KL[key * KPAD + 2 * tig + 8];
                s[oct][0] = 0.f; s[oct][1] = 0.f; s[oct][2] = 0.f; s[oct][3] = 0.f;
                mma16816(s[oct], aq, kh0, kh1, s[oct]);
                mma16816(s[oct], aq, kl0, kl1, s[oct]);
            }

            // causal mask on diagonal-crossing tiles only
            if (kbase + 63 > qmin) {
                const int ql0 = qmin + g;
                #pragma unroll
                for (int oct = 0; oct < 8; oct++) {
                    const int k0 = kbase + oct * 8 + 2 * tig;
                    s[oct][0] = (k0     <= ql0    ) ? s[oct][0] : -1e30f;
                    s[oct][1] = (k0 + 1 <= ql0    ) ? s[oct][1] : -1e30f;
                    s[oct][2] = (k0     <= ql0 + 8) ? s[oct][2] : -1e30f;
                    s[oct][3] = (k0 + 1 <= ql0 + 8) ? s[oct][3] : -1e30f;
                }
            }

            // ---- P = exp2(s) directly in f16x2 (fixed-max softmax)
            unsigned ph0[8], ph1[8];             // rows g / g+8
            #pragma unroll
            for (int oct = 0; oct < 8; oct++) {
                ph0[oct] = ex2h2(h2u(__float22half2_rn(make_float2(s[oct][0], s[oct][1]))));
                ph1[oct] = ex2h2(h2u(__float22half2_rn(make_float2(s[oct][2], s[oct][3]))));
            }

            // ---- O += P V (single f16 V) ; row sums via ones-mma
            #pragma unroll
            for (int cc = 0; cc < 4; cc++) {
                unsigned pa[4];
                pa[0] = ph0[2 * cc];
                pa[1] = ph1[2 * cc];
                pa[2] = ph0[2 * cc + 1];
                pa[3] = ph1[2 * cc + 1];
                mma16816(ol, pa, ONES, ONES, ol);
                #pragma unroll
                for (int nt = 0; nt < 2; nt++) {
                    const int vrow = (nt * 8 + g) * VPAD + cc * 16;
                    const unsigned vh0 = *(const unsigned*)&VH[vrow + 2 * tig];
                    const unsigned vh1 = *(const unsigned*)&VH[vrow + 2 * tig + 8];
                    mma16816(o[nt], pa, vh0, vh1, o[nt]);
                }
            }
        }
        __syncthreads();
    }

    // normalize and store (ol[0]/ol[2] are exact f32 row sums for g / g+8)
    const float inv0 = 1.f / ol[0];
    const float inv1 = 1.f / ol[2];
    const int q0 = qbase + warp * 16 + g;
    float* out0 = g_att + ((size_t)b * 1024 + q0) * 64 + h * 16;
    float* out1 = out0 + 8 * 64;
    #pragma unroll
    for (int nt = 0; nt < 2; nt++) {
        *(float2*)&out0[nt * 8 + 2 * tig] = make_float2(o[nt][0] * inv0, o[nt][1] * inv0);
        *(float2*)&out1[nt * 8 + 2 * tig] = make_float2(o[nt][2] * inv1, o[nt][3] * inv1);
    }
}

// ---------------------------------------------------------------------------
// Kernel C: output projection via f16-split m16n8k16 mma.
// Block: 256 threads = 8 warps (4 m x 2 n), 128 tokens, 64 outputs. Grid 512.
// ---------------------------------------------------------------------------
__global__ __launch_bounds__(256) void proj_kernel(float* __restrict__ out) {
    extern __shared__ __half smp[];
    __half* Ahi = smp;                    // [128][72]
    __half* Alo = Ahi + 128 * 72;
    __half* Whi = Alo + 128 * 72;         // [64][72]
    __half* Wlo = Whi + 64 * 72;

    const int tid = threadIdx.x;
    const int blk = blockIdx.x;           // 0..511

    for (int i = tid; i < 512; i += 256) {
        const int row = i >> 3, c = i & 7;
        cp_async16(&Whi[row * 72 + c * 8], g_wph + row * 64 + c * 8);
        cp_async16(&Wlo[row * 72 + c * 8], g_wpl + row * 64 + c * 8);
    }
    cp_commit();

    const float* asrc = g_att + (size_t)blk * 8192;
    for (int i = tid; i < 2048; i += 256) {
        const int row = i >> 4, c4 = i & 15;
        const float4 v = *(const float4*)&asrc[row * 64 + c4 * 4];
        __half2 h01, l01, h23, l23;
        split2(make_float2(v.x, v.y), h01, l01);
        split2(make_float2(v.z, v.w), h23, l23);
        *(__half2*)&Ahi[row * 72 + c4 * 4]     = h01;
        *(__half2*)&Ahi[row * 72 + c4 * 4 + 2] = h23;
        *(__half2*)&Alo[row * 72 + c4 * 4]     = l01;
        *(__half2*)&Alo[row * 72 + c4 * 4 + 2] = l23;
    }
    cp_wait0();
    __syncthreads();

    const int warp = tid >> 5, lane = tid & 31;
    const int g = lane >> 2, tig = lane & 3;
    const int wm = warp >> 1;
    const int wn = warp & 1;
    const int r0 = wm * 32;
    const int n0 = wn * 32;

    float acc[2][4][4];
    #pragma unroll
    for (int mt = 0; mt < 2; mt++)
        #pragma unroll
        for (int oct = 0; oct < 4; oct++)
            #pragma unroll
            for (int i = 0; i < 4; i++) acc[mt][oct][i] = 0.f;

    #pragma unroll
    for (int kc = 0; kc < 4; kc++) {
        unsigned ahi[2][4], alo[2][4];
        #pragma unroll
        for (int mt = 0; mt < 2; mt++) {
            const int rb = r0 + mt * 16;
            ahi[mt][0] = *(const unsigned*)&Ahi[(rb + g)     * 72 + kc * 16 + 2 * tig];
            ahi[mt][1] = *(const unsigned*)&Ahi[(rb + g + 8) * 72 + kc * 16 + 2 * tig];
            ahi[mt][2] = *(const unsigned*)&Ahi[(rb + g)     * 72 + kc * 16 + 2 * tig + 8];
            ahi[mt][3] = *(const unsigned*)&Ahi[(rb + g + 8) * 72 + kc * 16 + 2 * tig + 8];
            alo[mt][0] = *(const unsigned*)&Alo[(rb + g)     * 72 + kc * 16 + 2 * tig];
            alo[mt][1] = *(const unsigned*)&Alo[(rb + g + 8) * 72 + kc * 16 + 2 * tig];
            alo[mt][2] = *(const unsigned*)&Alo[(rb + g)     * 72 + kc * 16 + 2 * tig + 8];
            alo[mt][3] = *(const unsigned*)&Alo[(rb + g + 8) * 72 + kc * 16 + 2 * tig + 8];
        }
        #pragma unroll
        for (int oct = 0; oct < 4; oct++) {
            const int col = n0 + oct * 8 + g;
            const unsigned bh0 = *(const unsigned*)&Whi[col * 72 + kc * 16 + 2 * tig];
            const unsigned bh1 = *(const unsigned*)&Whi[col * 72 + kc * 16 + 2 * tig + 8];
            const unsigned bl0 = *(const unsigned*)&Wlo[col * 72 + kc * 16 + 2 * tig];
            const unsigned bl1 = *(const unsigned*)&Wlo[col * 72 + kc * 16 + 2 * tig + 8];
            #pragma unroll
            for (int mt = 0; mt < 2; mt++) {
                mma16816(acc[mt][oct], ahi[mt], bh0, bh1, acc[mt][oct]);
                mma16816(acc[mt][oct], alo[mt], bh0, bh1, acc[mt][oct]);
                mma16816(acc[mt][oct], ahi[mt], bl0, bl1, acc[mt][oct]);
            }
        }
    }

    #pragma unroll
    for (int mt = 0; mt < 2; mt++) {
        const int trow = r0 + mt * 16 + g;
        #pragma unroll
        for (int oct = 0; oct < 4; oct++) {
            const float* c = acc[mt][oct];
            const int o = n0 + oct * 8 + 2 * tig;
            const size_t base = ((size_t)blk * 128 + trow) * 64 + o;
            *(float2*)&out[base]          = make_float2(c[0], c[1]);
            *(float2*)&out[base + 8 * 64] = make_float2(c[2], c[3]);
        }
    }
}

// ---------------------------------------------------------------------------
extern "C" void kernel_launch(void* const* d_in, const int* in_sizes, int n_in,
                              void* d_out, int out_size) {
    const float* x      = (const float*)d_in[0];
    const float* w_qkv  = (const float*)d_in[1];
    const float* w_proj = (const float*)d_in[2];
    float* out = (float*)d_out;

    const int qkv_smem  = (64 * 72 + 192 * 72) * 2 * (int)sizeof(__half);   // 73728 B
    const int proj_smem = (128 * 72 + 64 * 72) * 2 * (int)sizeof(__half);   // 55296 B
    cudaFuncSetAttribute(qkv_kernel, cudaFuncAttributeMaxDynamicSharedMemorySize, qkv_smem);
    cudaFuncSetAttribute(proj_kernel, cudaFuncAttributeMaxDynamicSharedMemorySize, proj_smem);

    splitw_kernel<<<32, 256>>>(w_qkv, w_proj);
    qkv_kernel<<<1024, 384, qkv_smem>>>(x);
    attn_kernel<<<dim3(256, 8), 256>>>();
    proj_kernel<<<512, 256, proj_smem>>>(out);
}

// round 17
// speedup vs baseline: 1.0962x; 1.0962x over previous
#include <cuda_runtime.h>
#include <cuda_fp16.h>
#include <cstddef>

#define NB 64
#define NT 1024
#define NC 64
#define NH 4
#define ND 16

typedef unsigned long long u64;

// Scratch (device globals — no allocation allowed)
__device__ float  g_q  [(size_t)NB * NT * 64];             // [n][64] fp32 Q, c = h*16+d
__device__ __half g_kh [(size_t)NB * NH * NT * ND];        // [bh][t][d] f16 hi
__device__ __half g_kl [(size_t)NB * NH * NT * ND];        // [bh][t][d] f16 lo
__device__ __half g_vth[(size_t)NB * NH * ND * NT];        // [bh][d][t] f16 (transposed)
__device__ float  g_att[(size_t)NB * NT * NC];             // [n][64] attention out
// Pre-split weights (computed once by splitw_kernel)
__device__ __half g_wqh[192 * 64];                         // w_qkv hi
__device__ __half g_wql[192 * 64];                         // w_qkv lo
__device__ __half g_wph[64 * 64];                          // w_proj hi
__device__ __half g_wpl[64 * 64];                          // w_proj lo

// ---- cp.async helpers ------------------------------------------------------
__device__ __forceinline__ void cp_async16(void* smem, const void* gptr) {
    unsigned s = (unsigned)__cvta_generic_to_shared(smem);
    asm volatile("cp.async.ca.shared.global [%0], [%1], 16;" :: "r"(s), "l"(gptr));
}
__device__ __forceinline__ void cp_commit() { asm volatile("cp.async.commit_group;"); }
__device__ __forceinline__ void cp_wait1()  { asm volatile("cp.async.wait_group 1;"); }
__device__ __forceinline__ void cp_wait0()  { asm volatile("cp.async.wait_group 0;"); }

// ---- misc ------------------------------------------------------------------
__device__ __forceinline__ unsigned ex2h2(unsigned x) {   // 2x f16 exp2 in one MUFU
    unsigned r;
    asm("ex2.approx.f16x2 %0, %1;" : "=r"(r) : "r"(x));
    return r;
}
__device__ __forceinline__ unsigned h2u(__half2 h) { return *(unsigned*)&h; }

// ldmatrix x4: four 8x8 b16 matrices; lane>>3 selects matrix, lane&7 the row.
__device__ __forceinline__ void ldsm4(unsigned& r0, unsigned& r1,
                                      unsigned& r2, unsigned& r3, const void* p) {
    unsigned a = (unsigned)__cvta_generic_to_shared(p);
    asm volatile("ldmatrix.sync.aligned.m8n8.x4.shared.b16 {%0,%1,%2,%3}, [%4];"
        : "=r"(r0), "=r"(r1), "=r"(r2), "=r"(r3) : "r"(a));
}

// mma.sync m16n8k16 f16 inputs, f32 accum. D and C may alias.
__device__ __forceinline__ void mma16816(float* d, const unsigned* a,
                                         unsigned b0, unsigned b1, const float* c) {
    asm volatile(
        "mma.sync.aligned.m16n8k16.row.col.f32.f16.f16.f32 "
        "{%0,%1,%2,%3}, {%4,%5,%6,%7}, {%8,%9}, {%10,%11,%12,%13};\n"
        : "=f"(d[0]), "=f"(d[1]), "=f"(d[2]), "=f"(d[3])
        : "r"(a[0]), "r"(a[1]), "r"(a[2]), "r"(a[3]), "r"(b0), "r"(b1),
          "f"(c[0]), "f"(c[1]), "f"(c[2]), "f"(c[3]));
}

__device__ __forceinline__ void split2(float2 v, __half2& hi, __half2& lo) {
    hi = __float22half2_rn(v);
    lo = __float22half2_rn(make_float2(v.x - __low2float(hi), v.y - __high2float(hi)));
}

// ---------------------------------------------------------------------------
// Kernel 0: one-shot weight split (w_qkv 192x64, w_proj 64x64 -> f16 hi/lo).
// ---------------------------------------------------------------------------
__global__ void splitw_kernel(const float* __restrict__ wq,
                              const float* __restrict__ wp) {
    const int i = blockIdx.x * 256 + threadIdx.x;     // float2 index, 0..8191
    if (i < 6144) {
        const float2 v = *(const float2*)&wq[2 * i];
        __half2 hi, lo;
        split2(v, hi, lo);
        *(__half2*)&g_wqh[2 * i] = hi;
        *(__half2*)&g_wql[2 * i] = lo;
    } else {
        const int j = i - 6144;                        // 0..2047
        const float2 v = *(const float2*)&wp[2 * j];
        __half2 hi, lo;
        split2(v, hi, lo);
        *(__half2*)&g_wph[2 * j] = hi;
        *(__half2*)&g_wpl[2 * j] = lo;
    }
}

// ---------------------------------------------------------------------------
// Kernel A: QKV projection via f16-split m16n8k16 mma.
// Block: 384 threads = 12 warps (2 m x 6 n), 64 tokens, all 192 outputs.
// ---------------------------------------------------------------------------
__global__ __launch_bounds__(384) void qkv_kernel(const float* __restrict__ x) {
    extern __shared__ __half smh[];
    __half* Xhi = smh;                    // [64][72]
    __half* Xlo = Xhi + 64 * 72;
    __half* Whi = Xlo + 64 * 72;          // [192][72]
    __half* Wlo = Whi + 192 * 72;

    const int tid = threadIdx.x;
    const int blk = blockIdx.x;           // 0..1023

    for (int i = tid; i < 1536; i += 384) {
        const int row = i >> 3, c = i & 7;
        cp_async16(&Whi[row * 72 + c * 8], g_wqh + row * 64 + c * 8);
        cp_async16(&Wlo[row * 72 + c * 8], g_wql + row * 64 + c * 8);
    }
    cp_commit();

    const float* xsrc = x + (size_t)blk * 4096;
    for (int i = tid; i < 1024; i += 384) {
        const int row = i >> 4, c4 = i & 15;
        const float4 v = *(const float4*)&xsrc[row * 64 + c4 * 4];
        __half2 h01, l01, h23, l23;
        split2(make_float2(v.x, v.y), h01, l01);
        split2(make_float2(v.z, v.w), h23, l23);
        *(__half2*)&Xhi[row * 72 + c4 * 4]     = h01;
        *(__half2*)&Xhi[row * 72 + c4 * 4 + 2] = h23;
        *(__half2*)&Xlo[row * 72 + c4 * 4]     = l01;
        *(__half2*)&Xlo[row * 72 + c4 * 4 + 2] = l23;
    }
    cp_wait0();
    __syncthreads();

    const int warp = tid >> 5, lane = tid & 31;
    const int g = lane >> 2, tig = lane & 3;
    const int wm = warp / 6;              // 0..1
    const int wn = warp % 6;              // 0..5
    const int r0 = wm * 32;
    const int n0 = wn * 32;

    float acc[2][4][4];
    #pragma unroll
    for (int mt = 0; mt < 2; mt++)
        #pragma unroll
        for (int oct = 0; oct < 4; oct++)
            #pragma unroll
            for (int i = 0; i < 4; i++) acc[mt][oct][i] = 0.f;

    #pragma unroll
    for (int kc = 0; kc < 4; kc++) {
        unsigned ahi[2][4], alo[2][4];
        #pragma unroll
        for (int mt = 0; mt < 2; mt++) {
            const int rb = r0 + mt * 16;
            ahi[mt][0] = *(const unsigned*)&Xhi[(rb + g)     * 72 + kc * 16 + 2 * tig];
            ahi[mt][1] = *(const unsigned*)&Xhi[(rb + g + 8) * 72 + kc * 16 + 2 * tig];
            ahi[mt][2] = *(const unsigned*)&Xhi[(rb + g)     * 72 + kc * 16 + 2 * tig + 8];
            ahi[mt][3] = *(const unsigned*)&Xhi[(rb + g + 8) * 72 + kc * 16 + 2 * tig + 8];
            alo[mt][0] = *(const unsigned*)&Xlo[(rb + g)     * 72 + kc * 16 + 2 * tig];
            alo[mt][1] = *(const unsigned*)&Xlo[(rb + g + 8) * 72 + kc * 16 + 2 * tig];
            alo[mt][2] = *(const unsigned*)&Xlo[(rb + g)     * 72 + kc * 16 + 2 * tig + 8];
            alo[mt][3] = *(const unsigned*)&Xlo[(rb + g + 8) * 72 + kc * 16 + 2 * tig + 8];
        }
        #pragma unroll
        for (int oct = 0; oct < 4; oct++) {
            const int col = n0 + oct * 8 + g;
            const unsigned bh0 = *(const unsigned*)&Whi[col * 72 + kc * 16 + 2 * tig];
            const unsigned bh1 = *(const unsigned*)&Whi[col * 72 + kc * 16 + 2 * tig + 8];
            const unsigned bl0 = *(const unsigned*)&Wlo[col * 72 + kc * 16 + 2 * tig];
            const unsigned bl1 = *(const unsigned*)&Wlo[col * 72 + kc * 16 + 2 * tig + 8];
            #pragma unroll
            for (int mt = 0; mt < 2; mt++) {
                mma16816(acc[mt][oct], ahi[mt], bh0, bh1, acc[mt][oct]);
                mma16816(acc[mt][oct], alo[mt], bh0, bh1, acc[mt][oct]);
                mma16816(acc[mt][oct], ahi[mt], bl0, bl1, acc[mt][oct]);
            }
        }
    }

    const int bb  = blk >> 4;
    const int t0i = (blk & 15) * 64;
    #pragma unroll
    for (int mt = 0; mt < 2; mt++) {
        const int trow = r0 + mt * 16 + g;
        #pragma unroll
        for (int oct = 0; oct < 4; oct++) {
            const float* c = acc[mt][oct];
            const int o = n0 + oct * 8 + 2 * tig;
            if (o < 64) {                           // Q fp32 [n][64]
                const size_t base = ((size_t)blk * 64 + trow) * 64 + o;
                *(float2*)&g_q[base]          = make_float2(c[0], c[1]);
                *(float2*)&g_q[base + 8 * 64] = make_float2(c[2], c[3]);
            } else if (o < 128) {                   // K f16 hi/lo [bh][t][d]
                const int hh = (o - 64) >> 4, d = (o - 64) & 15;
                const size_t base =
                    ((size_t)(bb * 4 + hh) * 1024 + t0i + trow) * 16 + d;
                __half2 h01, l01, h23, l23;
                split2(make_float2(c[0], c[1]), h01, l01);
                split2(make_float2(c[2], c[3]), h23, l23);
                *(__half2*)&g_kh[base]          = h01;
                *(__half2*)&g_kl[base]          = l01;
                *(__half2*)&g_kh[base + 8 * 16] = h23;
                *(__half2*)&g_kl[base + 8 * 16] = l23;
            } else {                                // V^T single f16 [bh][d][t]
                const int hh = (o - 128) >> 4, d0 = (o - 128) & 15;
                const size_t t = (size_t)t0i + trow;
                const size_t rowa = ((size_t)(bb * 4 + hh) * 16 + d0) * 1024;
                const size_t rowb = rowa + 1024;
                const __half2 h01 = __float22half2_rn(make_float2(c[0], c[1]));
                const __half2 h23 = __float22half2_rn(make_float2(c[2], c[3]));
                g_vth[rowa + t]     = __low2half(h01);
                g_vth[rowb + t]     = __high2half(h01);
                g_vth[rowa + t + 8] = __low2half(h23);
                g_vth[rowb + t + 8] = __high2half(h23);
            }
        }
    }
}

// ---------------------------------------------------------------------------
// Kernel B: causal flash attention (R15 structure, ldmatrix fragment loads).
// QK: Q single-f16 x K hi/lo (2 mma); AV: P f16 x V single-f16 (1 mma);
// fixed-max softmax via ex2.approx.f16x2; row sums via ones-MMA.
// Grid (256 bh, 8 qtiles of 128 q), block 256 threads = 8 warps.
// ---------------------------------------------------------------------------
__device__ __forceinline__ void attn_prefetch(
    __half* KhiB, __half* KloB, __half* VhiB,
    int bh, int kt, int tid)
{
    if (tid < 128) {
        const size_t kg = ((size_t)bh * 1024 + (size_t)kt * 64) * 16;
        const int r = tid >> 1, c = tid & 1;             // 64 rows x 2 chunks
        cp_async16(KhiB + r * 24 + c * 8, g_kh + kg + r * 16 + c * 8);
        cp_async16(KloB + r * 24 + c * 8, g_kl + kg + r * 16 + c * 8);
    } else {
        const int i = tid - 128;
        const int d = i >> 3, vc = i & 7;                // 16 rows x 8 chunks
        const size_t vg = ((size_t)bh * 16 + d) * 1024 + (size_t)kt * 64 + vc * 8;
        cp_async16(VhiB + d * 72 + vc * 8, g_vth + vg);
    }
}

__global__ __launch_bounds__(256) void attn_kernel() {
    __shared__ __align__(16) float  Qs[128 * 16];
    __shared__ __align__(16) __half Khi[2][64 * 24];   // rows padded to 24 halves
    __shared__ __align__(16) __half Klo[2][64 * 24];
    __shared__ __align__(16) __half Vhi[2][16 * 72];   // rows padded to 72 halves

    const int tid  = threadIdx.x;
    const int bh   = blockIdx.x;                 // 0..255
    const int qt   = 7 - (int)blockIdx.y;        // heavy q-tiles first
    const int warp = tid >> 5;                   // 0..7
    const int lane = tid & 31;
    const int g    = lane >> 2;
    const int tig  = lane & 3;
    const int lm   = lane >> 3;                  // ldmatrix matrix id 0..3
    const int lr   = lane & 7;                   // ldmatrix row 0..7
    const int b    = bh >> 2, h = bh & 3;
    const int qbase = qt * 128;

    attn_prefetch(Khi[0], Klo[0], Vhi[0], bh, 0, tid);
    cp_commit();

    // stage Q tile (128 q x 16 d)
    {
        const float* qsrc = g_q + ((size_t)b * 1024 + qbase) * 64 + h * 16;
        for (int i = tid; i < 2048; i += 256) {
            const int ql = i >> 4, d = i & 15;
            Qs[ql * 16 + d] = qsrc[(size_t)ql * 64 + d];
        }
    }
    __syncthreads();

    // Q fragment: single f16, scale = 1/sqrt(16) * log2(e) folded in
    const float qscale = 0.25f * 1.4426950408889634f;
    unsigned aq[4];
    {
        const int r0 = warp * 16 + g;
        #pragma unroll
        for (int i = 0; i < 4; i++) {
            const int r = (i & 1) ? r0 + 8 : r0;
            const int c = (i >> 1) ? 2 * tig + 8 : 2 * tig;
            float2 v = *(const float2*)&Qs[r * 16 + c];
            v.x *= qscale;  v.y *= qscale;
            aq[i] = h2u(__float22half2_rn(v));
        }
    }

    const int qmin = qbase + warp * 16;          // this warp's lowest q row
    const unsigned ONES = 0x3C003C00u;           // (1.0h, 1.0h)
    float ol[4];                                  // ones-mma row sums
    float o[2][4];
    #pragma unroll
    for (int i = 0; i < 4; i++) { ol[i] = 0.f; o[0][i] = 0.f; o[1][i] = 0.f; }

    const int ntiles = 2 * qt + 2;
    for (int kt = 0; kt < ntiles; kt++) {
        const int bf = kt & 1;
        if (kt + 1 < ntiles) {
            attn_prefetch(Khi[bf ^ 1], Klo[bf ^ 1], Vhi[bf ^ 1], bh, kt + 1, tid);
            cp_commit();
            cp_wait1();
        } else {
            cp_wait0();
        }
        __syncthreads();

        const int kbase = kt * 64;
        if (kbase <= qmin + 15) {                // skip fully-masked tiles
            const __half* KH = Khi[bf];
            const __half* KL = Klo[bf];
            const __half* VH = Vhi[bf];

            // ---- S = Q K^T  via ldmatrix.x4 (2 octets per load pair)
            float s[8][4];
            #pragma unroll
            for (int op = 0; op < 4; op++) {
                // matrices: m0/m1 -> octet 2op cols 0/8 ; m2/m3 -> octet 2op+1
                const int krow = (2 * op + (lm >> 1)) * 8 + lr;
                const int kcol = (lm & 1) * 8;
                unsigned h0, h1, h2, h3, l0, l1, l2, l3;
                ldsm4(h0, h1, h2, h3, &KH[krow * 24 + kcol]);
                ldsm4(l0, l1, l2, l3, &KL[krow * 24 + kcol]);
                float* s0 = s[2 * op];
                float* s1 = s[2 * op + 1];
                s0[0] = 0.f; s0[1] = 0.f; s0[2] = 0.f; s0[3] = 0.f;
                s1[0] = 0.f; s1[1] = 0.f; s1[2] = 0.f; s1[3] = 0.f;
                mma16816(s0, aq, h0, h1, s0);
                mma16816(s0, aq, l0, l1, s0);
                mma16816(s1, aq, h2, h3, s1);
                mma16816(s1, aq, l2, l3, s1);
            }

            // causal mask on diagonal-crossing tiles only
            if (kbase + 63 > qmin) {
                const int ql0 = qmin + g;
                #pragma unroll
                for (int oct = 0; oct < 8; oct++) {
                    const int k0 = kbase + oct * 8 + 2 * tig;
                    s[oct][0] = (k0     <= ql0    ) ? s[oct][0] : -1e30f;
                    s[oct][1] = (k0 + 1 <= ql0    ) ? s[oct][1] : -1e30f;
                    s[oct][2] = (k0     <= ql0 + 8) ? s[oct][2] : -1e30f;
                    s[oct][3] = (k0 + 1 <= ql0 + 8) ? s[oct][3] : -1e30f;
                }
            }

            // ---- P = exp2(s) directly in f16x2 (fixed-max softmax)
            unsigned ph0[8], ph1[8];             // rows g / g+8
            #pragma unroll
            for (int oct = 0; oct < 8; oct++) {
                ph0[oct] = ex2h2(h2u(__float22half2_rn(make_float2(s[oct][0], s[oct][1]))));
                ph1[oct] = ex2h2(h2u(__float22half2_rn(make_float2(s[oct][2], s[oct][3]))));
            }

            // ---- O += P V (single f16 V, ldmatrix) ; row sums via ones-mma
            #pragma unroll
            for (int cc = 0; cc < 4; cc++) {
                unsigned pa[4];
                pa[0] = ph0[2 * cc];
                pa[1] = ph1[2 * cc];
                pa[2] = ph0[2 * cc + 1];
                pa[3] = ph1[2 * cc + 1];
                mma16816(ol, pa, ONES, ONES, ol);
                // matrices: m0/m1 -> nt0 cols +0/+8 ; m2/m3 -> nt1
                unsigned v0, v1, v2, v3;
                const int vrow = (lm >> 1) * 8 + lr;
                const int vcol = cc * 16 + (lm & 1) * 8;
                ldsm4(v0, v1, v2, v3, &VH[vrow * 72 + vcol]);
                mma16816(o[0], pa, v0, v1, o[0]);
                mma16816(o[1], pa, v2, v3, o[1]);
            }
        }
        __syncthreads();
    }

    // normalize and store (ol[0]/ol[2] are exact f32 row sums for g / g+8)
    const float inv0 = 1.f / ol[0];
    const float inv1 = 1.f / ol[2];
    const int q0 = qbase + warp * 16 + g;
    float* out0 = g_att + ((size_t)b * 1024 + q0) * 64 + h * 16;
    float* out1 = out0 + 8 * 64;
    #pragma unroll
    for (int nt = 0; nt < 2; nt++) {
        *(float2*)&out0[nt * 8 + 2 * tig] = make_float2(o[nt][0] * inv0, o[nt][1] * inv0);
        *(float2*)&out1[nt * 8 + 2 * tig] = make_float2(o[nt][2] * inv1, o[nt][3] * inv1);
    }
}

// ---------------------------------------------------------------------------
// Kernel C: output projection via f16-split m16n8k16 mma.
// Block: 256 threads = 8 warps (4 m x 2 n), 128 tokens, 64 outputs. Grid 512.
// ---------------------------------------------------------------------------
__global__ __launch_bounds__(256) void proj_kernel(float* __restrict__ out) {
    extern __shared__ __half smp[];
    __half* Ahi = smp;                    // [128][72]
    __half* Alo = Ahi + 128 * 72;
    __half* Whi = Alo + 128 * 72;         // [64][72]
    __half* Wlo = Whi + 64 * 72;

    const int tid = threadIdx.x;
    const int blk = blockIdx.x;           // 0..511

    for (int i = tid; i < 512; i += 256) {
        const int row = i >> 3, c = i & 7;
        cp_async16(&Whi[row * 72 + c * 8], g_wph + row * 64 + c * 8);
        cp_async16(&Wlo[row * 72 + c * 8], g_wpl + row * 64 + c * 8);
    }
    cp_commit();

    const float* asrc = g_att + (size_t)blk * 8192;
    for (int i = tid; i < 2048; i += 256) {
        const int row = i >> 4, c4 = i & 15;
        const float4 v = *(const float4*)&asrc[row * 64 + c4 * 4];
        __half2 h01, l01, h23, l23;
        split2(make_float2(v.x, v.y), h01, l01);
        split2(make_float2(v.z, v.w), h23, l23);
        *(__half2*)&Ahi[row * 72 + c4 * 4]     = h01;
        *(__half2*)&Ahi[row * 72 + c4 * 4 + 2] = h23;
        *(__half2*)&Alo[row * 72 + c4 * 4]     = l01;
        *(__half2*)&Alo[row * 72 + c4 * 4 + 2] = l23;
    }
    cp_wait0();
    __syncthreads();

    const int warp = tid >> 5, lane = tid & 31;
    const int g = lane >> 2, tig = lane & 3;
    const int wm = warp >> 1;
    const int wn = warp & 1;
    const int r0 = wm * 32;
    const int n0 = wn * 32;

    float acc[2][4][4];
    #pragma unroll
    for (int mt = 0; mt < 2; mt++)
        #pragma unroll
        for (int oct = 0; oct < 4; oct++)
            #pragma unroll
            for (int i = 0; i < 4; i++) acc[mt][oct][i] = 0.f;

    #pragma unroll
    for (int kc = 0; kc < 4; kc++) {
        unsigned ahi[2][4], alo[2][4];
        #pragma unroll
        for (int mt = 0; mt < 2; mt++) {
            const int rb = r0 + mt * 16;
            ahi[mt][0] = *(const unsigned*)&Ahi[(rb + g)     * 72 + kc * 16 + 2 * tig];
            ahi[mt][1] = *(const unsigned*)&Ahi[(rb + g + 8) * 72 + kc * 16 + 2 * tig];
            ahi[mt][2] = *(const unsigned*)&Ahi[(rb + g)     * 72 + kc * 16 + 2 * tig + 8];
            ahi[mt][3] = *(const unsigned*)&Ahi[(rb + g + 8) * 72 + kc * 16 + 2 * tig + 8];
            alo[mt][0] = *(const unsigned*)&Alo[(rb + g)     * 72 + kc * 16 + 2 * tig];
            alo[mt][1] = *(const unsigned*)&Alo[(rb + g + 8) * 72 + kc * 16 + 2 * tig];
            alo[mt][2] = *(const unsigned*)&Alo[(rb + g)     * 72 + kc * 16 + 2 * tig + 8];
            alo[mt][3] = *(const unsigned*)&Alo[(rb + g + 8) * 72 + kc * 16 + 2 * tig + 8];
        }
        #pragma unroll
        for (int oct = 0; oct < 4; oct++) {
            const int col = n0 + oct * 8 + g;
            const unsigned bh0 = *(const unsigned*)&Whi[col * 72 + kc * 16 + 2 * tig];
            const unsigned bh1 = *(const unsigned*)&Whi[col * 72 + kc * 16 + 2 * tig + 8];
            const unsigned bl0 = *(const unsigned*)&Wlo[col * 72 + kc * 16 + 2 * tig];
            const unsigned bl1 = *(const unsigned*)&Wlo[col * 72 + kc * 16 + 2 * tig + 8];
            #pragma unroll
            for (int mt = 0; mt < 2; mt++) {
                mma16816(acc[mt][oct], ahi[mt], bh0, bh1, acc[mt][oct]);
                mma16816(acc[mt][oct], alo[mt], bh0, bh1, acc[mt][oct]);
                mma16816(acc[mt][oct], ahi[mt], bl0, bl1, acc[mt][oct]);
            }
        }
    }

    #pragma unroll
    for (int mt = 0; mt < 2; mt++) {
        const int trow = r0 + mt * 16 + g;
        #pragma unroll
        for (int oct = 0; oct < 4; oct++) {
            const float* c = acc[mt][oct];
            const int o = n0 + oct * 8 + 2 * tig;
            const size_t base = ((size_t)blk * 128 + trow) * 64 + o;
            *(float2*)&out[base]          = make_float2(c[0], c[1]);
            *(float2*)&out[base + 8 * 64] = make_float2(c[2], c[3]);
        }
    }
}

// ---------------------------------------------------------------------------
extern "C" void kernel_launch(void* const* d_in, const int* in_sizes, int n_in,
                              void* d_out, int out_size) {
    const float* x      = (const float*)d_in[0];
    const float* w_qkv  = (const float*)d_in[1];
    const float* w_proj = (const float*)d_in[2];
    float* out = (float*)d_out;

    const int qkv_smem  = (64 * 72 + 192 * 72) * 2 * (int)sizeof(__half);   // 73728 B
    const int proj_smem = (128 * 72 + 64 * 72) * 2 * (int)sizeof(__half);   // 55296 B
    cudaFuncSetAttribute(qkv_kernel, cudaFuncAttributeMaxDynamicSharedMemorySize, qkv_smem);
    cudaFuncSetAttribute(proj_kernel, cudaFuncAttributeMaxDynamicSharedMemorySize, proj_smem);

    splitw_kernel<<<32, 256>>>(w_qkv, w_proj);
    qkv_kernel<<<1024, 384, qkv_smem>>>(x);
    attn_kernel<<<dim3(256, 8), 256>>>();
    proj_kernel<<<512, 256, proj_smem>>>(out);
}